// round 17
// baseline (speedup 1.0000x reference)
#include <cuda_runtime.h>
#include <cuda_fp16.h>
#include <cuda_fp8.h>
#include <math.h>
#include <stdint.h>

#define N_NODES 50000
#define N_EDGES 800000
#define N_GRAPHS 512
#define IN_DIM 126
#define DIMH 128
#define LIN1_DIM 64
#define BN_EPS 1e-5f

#define SCAN_NB 49   // ceil(50000/1024)
#define KPAIRS 64    // 128 k / 2 per u32 (fp16 planes)
#define KQUADS 32    // 128 k / 4 per u32 (fp8 feature rows)
#define FSCALE 0.0625f   // stored = value/16
#define FISCALE 16.0f

// ---------------- device scratch ----------------
__device__ uint32_t g_f8[N_NODES * KQUADS];    // features, fp8 e4m3 (value/16), 128B rows
__device__ uint32_t g_ah[N_NODES * KPAIRS];    // agg output, packed fp16 (true values)
__device__ uint32_t g_wsp[6 * KPAIRS * 128];   // pre-split fp16 weights, slot-major
__device__ int      g_cnt[N_NODES + 64];       // counts + 64 tail flags
__device__ int      g_bval[64];
__device__ int      g_off[N_NODES + 1];
__device__ int      g_cur[N_NODES];
__device__ int      g_srcs[N_EDGES];
__device__ int      g_gstart[N_GRAPHS + 1];

// ---------------- fp8 helpers ----------------
__device__ __forceinline__ float4 fp8x4_decode(uint32_t v) {
    __half2_raw h0 = __nv_cvt_fp8x2_to_halfraw2((__nv_fp8x2_storage_t)(v & 0xFFFF), __NV_E4M3);
    __half2_raw h1 = __nv_cvt_fp8x2_to_halfraw2((__nv_fp8x2_storage_t)(v >> 16), __NV_E4M3);
    float2 a = __half22float2(*(__half2*)&h0);
    float2 b = __half22float2(*(__half2*)&h1);
    return make_float4(a.x, a.y, b.x, b.y);
}

// ---------------- CSR build ----------------
__global__ void count_kernel(const int* __restrict__ dst) {
    int i = blockIdx.x * blockDim.x + threadIdx.x;
    if (i < N_EDGES) atomicAdd(&g_cnt[dst[i]], 1);
}

__global__ void scan_onepass_kernel() {
    __shared__ int ws[32];
    __shared__ int s_prefix;
    const int b = blockIdx.x;
    int i = b * 1024 + threadIdx.x;
    int lane = threadIdx.x & 31, wid = threadIdx.x >> 5;
    int v = (i < N_NODES) ? g_cnt[i] : 0;
    int x = v;
    #pragma unroll
    for (int o = 1; o < 32; o <<= 1) {
        int t = __shfl_up_sync(0xFFFFFFFFu, x, o);
        if (lane >= o) x += t;
    }
    if (lane == 31) ws[wid] = x;
    __syncthreads();
    if (wid == 0) {
        int s = ws[lane];
        #pragma unroll
        for (int o = 1; o < 32; o <<= 1) {
            int t = __shfl_up_sync(0xFFFFFFFFu, s, o);
            if (lane >= o) s += t;
        }
        ws[lane] = s;
    }
    __syncthreads();
    int incl  = x + (wid > 0 ? ws[wid - 1] : 0);
    int total = ws[31];
    if (threadIdx.x == 0) {
        g_bval[b] = total;
        __threadfence();
        atomicExch(&g_cnt[N_NODES + b], 1);
        s_prefix = 0;
    }
    __syncthreads();
    if (threadIdx.x < b) {
        while (atomicAdd(&g_cnt[N_NODES + threadIdx.x], 0) == 0) { }
        atomicAdd(&s_prefix, g_bval[threadIdx.x]);
    }
    __syncthreads();
    int excl = s_prefix + incl - v;
    if (i < N_NODES) { g_off[i] = excl; g_cur[i] = excl; }
    if (b == SCAN_NB - 1 && threadIdx.x == 0)
        g_off[N_NODES] = s_prefix + total;
}

__global__ void scatter_kernel(const int* __restrict__ src, const int* __restrict__ dst) {
    int i = blockIdx.x * blockDim.x + threadIdx.x;
    if (i < N_EDGES) {
        int p = atomicAdd(&g_cur[dst[i]], 1);
        g_srcs[p] = src[i];
    }
}

// pad x [N,126] fp32 -> g_f8 [N,32] fp8 (value/16)
__global__ void pad_x_kernel(const float* __restrict__ x) {
    int i = blockIdx.x * blockDim.x + threadIdx.x;
    if (i < N_NODES * KQUADS) {
        int n = i >> 5, p = i & 31;
        int c = 4 * p;
        float v0 = (c     < IN_DIM) ? x[n * IN_DIM + c    ] : 0.0f;
        float v1 = (c + 1 < IN_DIM) ? x[n * IN_DIM + c + 1] : 0.0f;
        float v2 = (c + 2 < IN_DIM) ? x[n * IN_DIM + c + 2] : 0.0f;
        float v3 = (c + 3 < IN_DIM) ? x[n * IN_DIM + c + 3] : 0.0f;
        __nv_fp8x2_storage_t lo = __nv_cvt_float2_to_fp8x2(
            make_float2(v0 * FSCALE, v1 * FSCALE), __NV_SATFINITE, __NV_E4M3);
        __nv_fp8x2_storage_t hi = __nv_cvt_float2_to_fp8x2(
            make_float2(v2 * FSCALE, v3 * FSCALE), __NV_SATFINITE, __NV_E4M3);
        g_f8[i] = (uint32_t)lo | ((uint32_t)hi << 16);
    }
}

__global__ void gstart_kernel(const int* __restrict__ batch) {
    int i = blockIdx.x * blockDim.x + threadIdx.x;
    if (i >= N_NODES) return;
    int b = batch[i];
    int bp = (i == 0) ? -1 : batch[i - 1];
    for (int gg = bp + 1; gg <= b; gg++) g_gstart[gg] = i;
    if (i == N_NODES - 1)
        for (int gg = b + 1; gg <= N_GRAPHS; gg++) g_gstart[gg] = N_NODES;
}

// ---------------- weight pre-split: fp32 [K,128] -> packed half2 ------------
__global__ void wsplit_kernel(const float* __restrict__ w1a, const float* __restrict__ w2a,
                              const float* __restrict__ w1b, const float* __restrict__ w2b,
                              const float* __restrict__ w1c, const float* __restrict__ w2c,
                              int Kw1) {
    int slot = blockIdx.y;
    const float* w = (slot == 0) ? w1a : (slot == 1) ? w2a : (slot == 2) ? w1b
                   : (slot == 3) ? w2b : (slot == 4) ? w1c : w2c;
    int Kw = (slot == 0) ? Kw1 : DIMH;
    int i = blockIdx.x * blockDim.x + threadIdx.x;
    if (i >= KPAIRS * 128) return;
    int kp = i >> 7, n = i & 127;
    int k0 = 2 * kp, k1 = k0 + 1;
    float v0 = (k0 < Kw) ? w[k0 * DIMH + n] : 0.0f;
    float v1 = (k1 < Kw) ? w[k1 * DIMH + n] : 0.0f;
    __half2 h = __floats2half2_rn(v0, v1);
    g_wsp[slot * KPAIRS * 128 + i] = *(uint32_t*)&h;
}

// ---------------- aggregation: warp/node over fp8 rows (1 u32/lane) ---------
__global__ __launch_bounds__(256) void agg_kernel(const uint32_t* __restrict__ F8,
                                                  uint32_t* __restrict__ oh) {
    int warp = (blockIdx.x * blockDim.x + threadIdx.x) >> 5;
    int lane = threadIdx.x & 31;
    if (warp >= N_NODES) return;
    int s = g_off[warp], e = g_off[warp + 1];
    float4 acc = fp8x4_decode(F8[warp * KQUADS + lane]);
    int j = s;
    for (; j + 4 <= e; j += 4) {
        int s0 = g_srcs[j];
        int s1 = g_srcs[j + 1];
        int s2 = g_srcs[j + 2];
        int s3 = g_srcs[j + 3];
        uint32_t u0 = F8[s0 * KQUADS + lane];
        uint32_t u1 = F8[s1 * KQUADS + lane];
        uint32_t u2 = F8[s2 * KQUADS + lane];
        uint32_t u3 = F8[s3 * KQUADS + lane];
        float4 f0 = fp8x4_decode(u0);
        float4 f1 = fp8x4_decode(u1);
        float4 f2 = fp8x4_decode(u2);
        float4 f3 = fp8x4_decode(u3);
        acc.x += (f0.x + f1.x) + (f2.x + f3.x);
        acc.y += (f0.y + f1.y) + (f2.y + f3.y);
        acc.z += (f0.z + f1.z) + (f2.z + f3.z);
        acc.w += (f0.w + f1.w) + (f2.w + f3.w);
    }
    for (; j < e; j++) {
        float4 f = fp8x4_decode(F8[g_srcs[j] * KQUADS + lane]);
        acc.x += f.x; acc.y += f.y; acc.z += f.z; acc.w += f.w;
    }
    // rescale to true values, pack fp16
    __half2 h0 = __floats2half2_rn(acc.x * FISCALE, acc.y * FISCALE);
    __half2 h1 = __floats2half2_rn(acc.z * FISCALE, acc.w * FISCALE);
    uint2 hv = make_uint2(*(uint32_t*)&h0, *(uint32_t*)&h1);
    *(uint2*)&oh[warp * KPAIRS + 2 * lane] = hv;
}

// ---------------- fp16 mma ----------------
__device__ __forceinline__ void mma_f16(float* c, const uint32_t* a, const uint32_t* b) {
    asm volatile(
        "mma.sync.aligned.m16n8k16.row.col.f32.f16.f16.f32 "
        "{%0,%1,%2,%3}, {%4,%5,%6,%7}, {%8,%9}, {%0,%1,%2,%3};\n"
        : "+f"(c[0]), "+f"(c[1]), "+f"(c[2]), "+f"(c[3])
        : "r"(a[0]), "r"(a[1]), "r"(a[2]), "r"(a[3]), "r"(b[0]), "r"(b[1]));
}

// ---------------- fused double-GEMM per GIN layer, fp16, fp8 output ---------
#define AST 20
#define BST 136
#define HST 68
#define SM_AH 0
#define SM_B  (64 * AST)
#define SM_HH (SM_B + 16 * BST)
#define SMEM_U32 (SM_HH + 64 * HST)

__global__ __launch_bounds__(256, 3) void layer_gemm_kernel(
    const uint32_t* __restrict__ Ahg,
    const uint32_t* __restrict__ W1p, const float* __restrict__ b1,
    const float* __restrict__ gamma, const float* __restrict__ beta,
    const float* __restrict__ mean, const float* __restrict__ var,
    const uint32_t* __restrict__ W2p, const float* __restrict__ b2,
    uint32_t* __restrict__ OUT8)
{
    extern __shared__ uint32_t sm[];
    uint32_t* Ah = sm + SM_AH;
    uint32_t* B  = sm + SM_B;
    uint32_t* Hh = sm + SM_HH;

    const int tid  = threadIdx.x;
    const int wid  = tid >> 5;
    const int lane = tid & 31;
    const int g    = lane >> 2;
    const int tig  = lane & 3;
    const int wm   = wid & 1;
    const int wn   = wid >> 1;
    const int row0 = blockIdx.x * 64;

    float acc[2][4][4];

    // =========== GEMM1 ===========
    #pragma unroll
    for (int mi = 0; mi < 2; mi++)
        #pragma unroll
        for (int ni = 0; ni < 4; ni++)
            #pragma unroll
            for (int r = 0; r < 4; r++) acc[mi][ni][r] = 0.0f;

    for (int c = 0; c < 4; c++) {
        {
            int r = tid >> 2, kp4 = (tid & 3) * 4;
            int gr = row0 + r;
            uint4 vh = make_uint4(0, 0, 0, 0);
            if (gr < N_NODES)
                vh = *(const uint4*)&Ahg[gr * KPAIRS + c * 16 + kp4];
            *(uint4*)&Ah[r * AST + kp4] = vh;
        }
        #pragma unroll
        for (int l = 0; l < 2; l++) {
            int idx = tid + l * 256;
            int kp = idx >> 5;
            int c4 = (idx & 31) * 4;
            uint4 v = *(const uint4*)&W1p[(c * 16 + kp) * 128 + c4];
            *(uint4*)&B[kp * BST + c4] = v;
        }
        __syncthreads();

        #pragma unroll
        for (int ks = 0; ks < 2; ks++) {
            const int kk2 = ks * 8;
            uint32_t a_hi[2][4];
            #pragma unroll
            for (int mi = 0; mi < 2; mi++) {
                int rm = wm * 32 + mi * 16;
                a_hi[mi][0] = Ah[(rm + g    ) * AST + kk2 + tig    ];
                a_hi[mi][1] = Ah[(rm + g + 8) * AST + kk2 + tig    ];
                a_hi[mi][2] = Ah[(rm + g    ) * AST + kk2 + tig + 4];
                a_hi[mi][3] = Ah[(rm + g + 8) * AST + kk2 + tig + 4];
            }
            #pragma unroll
            for (int ni = 0; ni < 4; ni++) {
                int cn = wn * 32 + ni * 8;
                uint32_t b[2];
                b[0] = B[(kk2 + tig    ) * BST + cn + g];
                b[1] = B[(kk2 + tig + 4) * BST + cn + g];
                #pragma unroll
                for (int mi = 0; mi < 2; mi++)
                    mma_f16(acc[mi][ni], a_hi[mi], b);
            }
        }
        __syncthreads();
    }

    // ---- epilogue1: BN+ReLU -> Hh (plain fp16) ----
    {
        float sc[4][2], sh[4][2];
        #pragma unroll
        for (int ni = 0; ni < 4; ni++) {
            #pragma unroll
            for (int j = 0; j < 2; j++) {
                int col = wn * 32 + ni * 8 + 2 * tig + j;
                float s = gamma[col] * rsqrtf(var[col] + BN_EPS);
                sc[ni][j] = s;
                sh[ni][j] = beta[col] - mean[col] * s + b1[col] * s;
            }
        }
        #pragma unroll
        for (int mi = 0; mi < 2; mi++) {
            int r0 = wm * 32 + mi * 16 + g;
            int r1 = r0 + 8;
            #pragma unroll
            for (int ni = 0; ni < 4; ni++) {
                int kp = wn * 16 + ni * 4 + tig;
                float o00 = fmaxf(acc[mi][ni][0] * sc[ni][0] + sh[ni][0], 0.0f);
                float o01 = fmaxf(acc[mi][ni][1] * sc[ni][1] + sh[ni][1], 0.0f);
                float o10 = fmaxf(acc[mi][ni][2] * sc[ni][0] + sh[ni][0], 0.0f);
                float o11 = fmaxf(acc[mi][ni][3] * sc[ni][1] + sh[ni][1], 0.0f);
                __half2 h0 = __floats2half2_rn(o00, o01);
                __half2 h1 = __floats2half2_rn(o10, o11);
                Hh[r0 * HST + kp] = *(uint32_t*)&h0;
                Hh[r1 * HST + kp] = *(uint32_t*)&h1;
            }
        }
    }

    // =========== GEMM2 ===========
    #pragma unroll
    for (int mi = 0; mi < 2; mi++)
        #pragma unroll
        for (int ni = 0; ni < 4; ni++)
            #pragma unroll
            for (int r = 0; r < 4; r++) acc[mi][ni][r] = 0.0f;

    for (int c = 0; c < 4; c++) {
        __syncthreads();
        #pragma unroll
        for (int l = 0; l < 2; l++) {
            int idx = tid + l * 256;
            int kp = idx >> 5;
            int c4 = (idx & 31) * 4;
            uint4 v = *(const uint4*)&W2p[(c * 16 + kp) * 128 + c4];
            *(uint4*)&B[kp * BST + c4] = v;
        }
        __syncthreads();

        #pragma unroll
        for (int ks = 0; ks < 2; ks++) {
            const int kp0 = c * 16 + ks * 8;
            uint32_t a_hi[2][4];
            #pragma unroll
            for (int mi = 0; mi < 2; mi++) {
                int rm = wm * 32 + mi * 16;
                a_hi[mi][0] = Hh[(rm + g    ) * HST + kp0 + tig    ];
                a_hi[mi][1] = Hh[(rm + g + 8) * HST + kp0 + tig    ];
                a_hi[mi][2] = Hh[(rm + g    ) * HST + kp0 + tig + 4];
                a_hi[mi][3] = Hh[(rm + g + 8) * HST + kp0 + tig + 4];
            }
            const int kb = ks * 8;
            #pragma unroll
            for (int ni = 0; ni < 4; ni++) {
                int cn = wn * 32 + ni * 8;
                uint32_t b[2];
                b[0] = B[(kb + tig    ) * BST + cn + g];
                b[1] = B[(kb + tig + 4) * BST + cn + g];
                #pragma unroll
                for (int mi = 0; mi < 2; mi++)
                    mma_f16(acc[mi][ni], a_hi[mi], b);
            }
        }
    }

    // ---- epilogue2: bias + ReLU -> fp8 (value/16) via lane-pair pack ----
    float bb[4][2];
    #pragma unroll
    for (int ni = 0; ni < 4; ni++) {
        #pragma unroll
        for (int j = 0; j < 2; j++)
            bb[ni][j] = b2[wn * 32 + ni * 8 + 2 * tig + j];
    }
    #pragma unroll
    for (int mi = 0; mi < 2; mi++) {
        int r0 = row0 + wm * 32 + mi * 16 + g;
        int r1 = r0 + 8;
        #pragma unroll
        for (int ni = 0; ni < 4; ni++) {
            int c0 = wn * 32 + ni * 8 + 2 * tig;
            // row r0 pair
            {
                float ox = fmaxf(acc[mi][ni][0] + bb[ni][0], 0.0f) * FSCALE;
                float oy = fmaxf(acc[mi][ni][1] + bb[ni][1], 0.0f) * FSCALE;
                uint32_t my = (uint32_t)__nv_cvt_float2_to_fp8x2(
                    make_float2(ox, oy), __NV_SATFINITE, __NV_E4M3);
                uint32_t other = __shfl_xor_sync(0xFFFFFFFFu, my, 1);
                if ((tig & 1) == 0 && r0 < N_NODES)
                    OUT8[r0 * KQUADS + (c0 >> 2)] = (my & 0xFFFF) | (other << 16);
            }
            // row r1 pair
            {
                float ox = fmaxf(acc[mi][ni][2] + bb[ni][0], 0.0f) * FSCALE;
                float oy = fmaxf(acc[mi][ni][3] + bb[ni][1], 0.0f) * FSCALE;
                uint32_t my = (uint32_t)__nv_cvt_float2_to_fp8x2(
                    make_float2(ox, oy), __NV_SATFINITE, __NV_E4M3);
                uint32_t other = __shfl_xor_sync(0xFFFFFFFFu, my, 1);
                if ((tig & 1) == 0 && r1 < N_NODES)
                    OUT8[r1 * KQUADS + (c0 >> 2)] = (my & 0xFFFF) | (other << 16);
            }
        }
    }
}

// ---------------- fused pool (segment sum over fp8) + MLP head --------------
__global__ void pool_head_kernel(const uint32_t* __restrict__ h8,
                                 const float* __restrict__ l1w, const float* __restrict__ l1b,
                                 const float* __restrict__ l2w, const float* __restrict__ l2b,
                                 float* __restrict__ out) {
    __shared__ float hg[DIMH];
    __shared__ float o1[LIN1_DIM];
    int gph = blockIdx.x;
    int t = threadIdx.x;            // 0..127 -> feature t
    int u = t >> 2, sub = t & 3;    // u32 index, byte within
    int s = g_gstart[gph], e = g_gstart[gph + 1];
    float a0 = 0.f;
    for (int r = s; r < e; r++) {
        uint32_t w = h8[r * KQUADS + u];
        uint16_t b = (uint16_t)((w >> (8 * sub)) & 0xFF);
        __half2_raw hr = __nv_cvt_fp8x2_to_halfraw2((__nv_fp8x2_storage_t)b, __NV_E4M3);
        a0 += __half2float(((__half2*)&hr)->x);
    }
    hg[t] = a0 * FISCALE;
    __syncthreads();
    if (t < LIN1_DIM) {
        float s2 = l1b[t];
        #pragma unroll 8
        for (int k = 0; k < DIMH; k++) s2 += hg[k] * l1w[k * LIN1_DIM + t];
        o1[t] = fmaxf(s2, 0.0f);
    }
    __syncthreads();
    if (t == 0) {
        float s2 = l2b[0];
        #pragma unroll 8
        for (int j = 0; j < LIN1_DIM; j++) s2 += o1[j] * l2w[j];
        out[gph] = 1.0f / (1.0f + expf(-s2));
    }
}

// ---------------- launch ----------------
extern "C" void kernel_launch(void* const* d_in, const int* in_sizes, int n_in,
                              void* d_out, int out_size) {
    const float* x          = (const float*)d_in[0];
    const int*   edge_index = (const int*)d_in[1];
    const int*   batch      = (const int*)d_in[2];
    const float* w[3][7];
    const float* b2[3];
    for (int l = 0; l < 3; l++) {
        int base = 3 + l * 8;
        w[l][0] = (const float*)d_in[base + 0];
        w[l][1] = (const float*)d_in[base + 1];
        w[l][2] = (const float*)d_in[base + 2];
        w[l][3] = (const float*)d_in[base + 3];
        w[l][4] = (const float*)d_in[base + 4];
        w[l][5] = (const float*)d_in[base + 5];
        w[l][6] = (const float*)d_in[base + 6];
        b2[l]   = (const float*)d_in[base + 7];
    }
    const float* l1w = (const float*)d_in[27];
    const float* l1b = (const float*)d_in[28];
    const float* l2w = (const float*)d_in[29];
    const float* l2b = (const float*)d_in[30];
    float* out = (float*)d_out;

    const int* e_src = edge_index;
    const int* e_dst = edge_index + N_EDGES;

    static uint32_t* p_f8   = nullptr;
    static uint32_t* p_ah   = nullptr;
    static uint32_t* p_wsp  = nullptr;
    static int*      p_cnt  = nullptr;
    static cudaStream_t s_aux = nullptr;
    static cudaEvent_t ev_fork = nullptr, ev_join = nullptr;
    if (!p_f8) {
        cudaGetSymbolAddress((void**)&p_f8,  g_f8);
        cudaGetSymbolAddress((void**)&p_ah,  g_ah);
        cudaGetSymbolAddress((void**)&p_wsp, g_wsp);
        cudaGetSymbolAddress((void**)&p_cnt, g_cnt);
        cudaFuncSetAttribute(layer_gemm_kernel,
                             cudaFuncAttributeMaxDynamicSharedMemorySize,
                             SMEM_U32 * 4);
        cudaStreamCreateWithFlags(&s_aux, cudaStreamNonBlocking);
        cudaEventCreateWithFlags(&ev_fork, cudaEventDisableTiming);
        cudaEventCreateWithFlags(&ev_join, cudaEventDisableTiming);
    }

    // ---- fork: aux stream runs CSR-independent setup ----
    cudaEventRecord(ev_fork, 0);
    cudaStreamWaitEvent(s_aux, ev_fork, 0);
    pad_x_kernel<<<(N_NODES * KQUADS + 255) / 256, 256, 0, s_aux>>>(x);
    gstart_kernel<<<(N_NODES + 255) / 256, 256, 0, s_aux>>>(batch);
    {
        dim3 grid((KPAIRS * 128 + 255) / 256, 6);
        wsplit_kernel<<<grid, 256, 0, s_aux>>>(w[0][0], w[0][6], w[1][0], w[1][6],
                                               w[2][0], w[2][6], IN_DIM);
    }
    cudaEventRecord(ev_join, s_aux);

    // ---- main stream: CSR build ----
    cudaMemsetAsync(p_cnt, 0, (N_NODES + 64) * sizeof(int));
    count_kernel<<<(N_EDGES + 255) / 256, 256>>>(e_dst);
    scan_onepass_kernel<<<SCAN_NB, 1024>>>();
    scatter_kernel<<<(N_EDGES + 255) / 256, 256>>>(e_src, e_dst);

    // ---- join before layers ----
    cudaStreamWaitEvent(0, ev_join, 0);

    const int GEMM_GRID = (N_NODES + 63) / 64;
    const int AGG_GRID  = (N_NODES * 32 + 255) / 256;
    const size_t SMEM   = SMEM_U32 * 4;

    // ---- 3 GIN layers ----
    for (int l = 0; l < 3; l++) {
        agg_kernel<<<AGG_GRID, 256>>>(p_f8, p_ah);
        layer_gemm_kernel<<<GEMM_GRID, 256, SMEM>>>(
            p_ah,
            p_wsp + (2 * l) * KPAIRS * 128, w[l][1], w[l][2], w[l][3],
            w[l][4], w[l][5],
            p_wsp + (2 * l + 1) * KPAIRS * 128, b2[l],
            p_f8);
    }

    // ---- fused pool + head ----
    pool_head_kernel<<<N_GRAPHS, 128>>>(p_f8, l1w, l1b, l2w, l2b, out);
}